// round 2
// baseline (speedup 1.0000x reference)
#include <cuda_runtime.h>

#define H 128
#define NB 3
#define SEQ 2048
#define G4 512

__device__ float  g_pre[NB * SEQ * G4];
__device__ float  g_ys1[NB * SEQ * H];
__device__ float4 g_Wp1[32 * G4];
__device__ float4 g_Wp2[32 * G4];
__device__ float  g_WT2[128 * G4];
__device__ float  g_a2[NB * H];
__device__ float  g_bb2[NB * H];

__device__ __forceinline__ float sigm(float x) { return 1.0f / (1.0f + __expf(-x)); }

// grid 6: 0..2 BN1+pre1 per branch; 3 pack Whh1; 4 pack Whh2; 5 pack Wih2^T
__global__ void __launch_bounds__(512) k_prep(
    const float* __restrict__ x,
    const float* __restrict__ g1, const float* __restrict__ b1,
    const float* __restrict__ Wih1, const float* __restrict__ Whh1,
    const float* __restrict__ bih1, const float* __restrict__ bhh1,
    const float* __restrict__ Wih2, const float* __restrict__ Whh2)
{
    const int bx = blockIdx.x, tid = threadIdx.x;
    if (bx == 5) {
        for (int i = tid; i < 128 * G4; i += 512) {
            int k = i >> 9, r = i & 511;
            g_WT2[i] = Wih2[r * 128 + k];
        }
        return;
    }
    if (bx >= 3) {
        const float* src = (bx == 3) ? Whh1 : Whh2;
        float4* dst = (bx == 3) ? g_Wp1 : g_Wp2;
        for (int i = tid; i < 32 * G4; i += 512) {
            int k4 = i >> 9, r = i & 511;
            const float* s = src + r * 128 + 4 * k4;
            dst[i] = make_float4(s[0], s[1], s[2], s[3]);
        }
        return;
    }
    __shared__ float a1[16], bb1[16];
    const int w = tid >> 5, lane = tid & 31;
    {
        float s = 0.f, sq = 0.f;
        for (int m = lane; m < 384; m += 32) {
            int n = m / 3, d = m - 3 * n;
            float v = x[(n * 48 + bx * 16 + w) * 3 + d];
            s += v; sq += v * v;
        }
        #pragma unroll
        for (int o = 16; o; o >>= 1) {
            s  += __shfl_xor_sync(0xffffffffu, s, o);
            sq += __shfl_xor_sync(0xffffffffu, sq, o);
        }
        if (lane == 0) {
            float mean = s * (1.0f / 384.0f);
            float var  = sq * (1.0f / 384.0f) - mean * mean;
            float a = g1[w] * rsqrtf(var + 1e-5f);
            a1[w] = a; bb1[w] = b1[w] - mean * a;
        }
    }
    __syncthreads();
    const int r = tid;
    const float w0 = Wih1[r * 3], w1 = Wih1[r * 3 + 1], w2 = Wih1[r * 3 + 2];
    const float bias = bih1[r] + bhh1[r];
    float* pre = g_pre + bx * (SEQ * G4);
    for (int s = 0; s < SEQ; s++) {
        int n = s & 127, t = s >> 7;
        const float* xp = x + (n * 48 + bx * 16 + t) * 3;
        float a = a1[t], bb = bb1[t];
        float x0 = fmaf(xp[0], a, bb);
        float x1 = fmaf(xp[1], a, bb);
        float x2 = fmaf(xp[2], a, bb);
        pre[s * G4 + r] = bias + w0 * x0 + w1 * x1 + w2 * x2;
    }
}

// one CTA per branch; 2048 serial steps
__global__ void __launch_bounds__(512) k_scan(
    const float* __restrict__ h0s, const float* __restrict__ c0s,
    float* __restrict__ dout, int layer)
{
    const int b = blockIdx.x, tid = threadIdx.x;
    __shared__ __align__(16) float sh_h[H];
    __shared__ float sh_g[G4];
    const float4* __restrict__ Wp = layer ? g_Wp2 : g_Wp1;
    const float*  __restrict__ pre = g_pre + b * (SEQ * G4);
    float* __restrict__ ob = layer ? (dout + b * (SEQ * H)) : (g_ys1 + b * (SEQ * H));

    float c = 0.f;
    if (tid < H) {
        sh_h[tid] = h0s[(2 * b + layer) * H + tid];
        c         = c0s[(2 * b + layer) * H + tid];
    }
    __syncthreads();
    const float4* wp = Wp + tid;
    for (int s = 0; s < SEQ; s++) {
        float acc = pre[s * G4 + tid];
        const float4* hp = (const float4*)sh_h;
        #pragma unroll
        for (int k4 = 0; k4 < 32; k4++) {
            float4 wv = wp[k4 * G4];
            float4 hv = hp[k4];
            acc = fmaf(wv.x, hv.x, acc);
            acc = fmaf(wv.y, hv.y, acc);
            acc = fmaf(wv.z, hv.z, acc);
            acc = fmaf(wv.w, hv.w, acc);
        }
        sh_g[tid] = acc;
        __syncthreads();
        if (tid < H) {
            float ig = sigm(sh_g[tid]);
            float fg = sigm(sh_g[H + tid]);
            float gg = tanhf(sh_g[2 * H + tid]);
            float og = sigm(sh_g[3 * H + tid]);
            c = fg * c + ig * gg;
            float h = og * tanhf(c);
            ob[s * H + tid] = h;
            sh_h[tid] = h;
        }
        __syncthreads();
    }
}

// BN2 stats per branch: channel ch over a(16) x l(128)
__global__ void __launch_bounds__(512) k_bn2(
    const float* __restrict__ g2, const float* __restrict__ b2)
{
    const int b = blockIdx.x, w = threadIdx.x >> 5, lane = threadIdx.x & 31;
    const float* ys = g_ys1 + b * (SEQ * H);
    for (int ch = w; ch < H; ch += 16) {
        float s = 0.f, sq = 0.f;
        for (int m = lane; m < 2048; m += 32) {
            int a = m >> 7, l = m & 127;
            float v = ys[(a * 128 + ch) * H + l];
            s += v; sq += v * v;
        }
        #pragma unroll
        for (int o = 16; o; o >>= 1) {
            s  += __shfl_xor_sync(0xffffffffu, s, o);
            sq += __shfl_xor_sync(0xffffffffu, sq, o);
        }
        if (lane == 0) {
            float mean = s * (1.0f / 2048.0f);
            float var  = sq * (1.0f / 2048.0f) - mean * mean;
            float a2 = g2[ch] * rsqrtf(var + 1e-5f);
            g_a2[b * H + ch]  = a2;
            g_bb2[b * H + ch] = b2[ch] - mean * a2;
        }
    }
}

// pre2[s2][r] = bias2[r] + Wih2[r,:] . (a2[ch]*ys1[s1] + bb2[ch])
// s1 = (s2%16)*128 + s2/16 ; ch = s2/16
__global__ void __launch_bounds__(512) k_pre2(
    const float* __restrict__ bih2, const float* __restrict__ bhh2)
{
    const int b = blockIdx.x >> 6, grp = blockIdx.x & 63, s0 = grp * 32;
    const int tid = threadIdx.x, r = tid;
    __shared__ float sh_x[32][128];
    const float* ys = g_ys1 + b * (SEQ * H);
    for (int i = tid; i < 32 * 128; i += 512) {
        int row = i >> 7, k = i & 127;
        int s2 = s0 + row;
        int ch = s2 >> 4;
        int s1 = ((s2 & 15) << 7) + ch;
        sh_x[row][k] = fmaf(g_a2[b * H + ch], ys[s1 * H + k], g_bb2[b * H + ch]);
    }
    __syncthreads();
    float acc[32];
    #pragma unroll
    for (int i = 0; i < 32; i++) acc[i] = 0.f;
    for (int k = 0; k < 128; k++) {
        float w = g_WT2[k * G4 + r];
        #pragma unroll
        for (int i = 0; i < 32; i++) acc[i] = fmaf(w, sh_x[i][k], acc[i]);
    }
    float bias = bih2[r] + bhh2[r];
    float* pre = g_pre + b * (SEQ * G4);
    #pragma unroll
    for (int i = 0; i < 32; i++) pre[(s0 + i) * G4 + r] = acc[i] + bias;
}

extern "C" void kernel_launch(void* const* d_in, const int* in_sizes, int n_in,
                              void* d_out, int out_size)
{
    const float* x    = (const float*)d_in[0];
    const float* g1   = (const float*)d_in[1];
    const float* b1   = (const float*)d_in[2];
    const float* Wih1 = (const float*)d_in[3];
    const float* Whh1 = (const float*)d_in[4];
    const float* bih1 = (const float*)d_in[5];
    const float* bhh1 = (const float*)d_in[6];
    const float* g2   = (const float*)d_in[7];
    const float* b2   = (const float*)d_in[8];
    const float* Wih2 = (const float*)d_in[9];
    const float* Whh2 = (const float*)d_in[10];
    const float* bih2 = (const float*)d_in[11];
    const float* bhh2 = (const float*)d_in[12];
    const float* h0s  = (const float*)d_in[13];
    const float* c0s  = (const float*)d_in[14];
    float* out = (float*)d_out;

    k_prep<<<6, 512>>>(x, g1, b1, Wih1, Whh1, bih1, bhh1, Wih2, Whh2);
    k_scan<<<NB, 512>>>(h0s, c0s, out, 0);
    k_bn2<<<NB, 512>>>(g2, b2);
    k_pre2<<<NB * 64, 512>>>(bih2, bhh2);
    k_scan<<<NB, 512>>>(h0s, c0s, out, 1);
}

// round 4
// speedup vs baseline: 2.2727x; 2.2727x over previous
#include <cuda_runtime.h>
#include <cstdint>

#define H 128
#define NB 3
#define SEQ 2048
#define G4 512

__device__ float g_pre[NB * SEQ * G4];
__device__ float g_ys1[NB * SEQ * H];
__device__ float g_WT2[128 * G4];
__device__ float g_a2[NB * H];
__device__ float g_bb2[NB * H];

__device__ __forceinline__ float sigm(float x) { return 1.0f / (1.0f + __expf(-x)); }

// grid 4: 0..2 BN1+pre1 per branch; 3 pack Wih2^T
__global__ void __launch_bounds__(512) k_prep(
    const float* __restrict__ x,
    const float* __restrict__ g1, const float* __restrict__ b1,
    const float* __restrict__ Wih1,
    const float* __restrict__ bih1, const float* __restrict__ bhh1,
    const float* __restrict__ Wih2)
{
    const int bx = blockIdx.x, tid = threadIdx.x;
    if (bx == 3) {
        for (int i = tid; i < 128 * G4; i += 512) {
            int k = i >> 9, r = i & 511;
            g_WT2[i] = Wih2[r * 128 + k];
        }
        return;
    }
    __shared__ float a1[16], bb1[16];
    const int w = tid >> 5, lane = tid & 31;
    {
        float s = 0.f, sq = 0.f;
        for (int m = lane; m < 384; m += 32) {
            int n = m / 3, d = m - 3 * n;
            float v = x[(n * 48 + bx * 16 + w) * 3 + d];
            s += v; sq += v * v;
        }
        #pragma unroll
        for (int o = 16; o; o >>= 1) {
            s  += __shfl_xor_sync(0xffffffffu, s, o);
            sq += __shfl_xor_sync(0xffffffffu, sq, o);
        }
        if (lane == 0) {
            float mean = s * (1.0f / 384.0f);
            float var  = sq * (1.0f / 384.0f) - mean * mean;
            float a = g1[w] * rsqrtf(var + 1e-5f);
            a1[w] = a; bb1[w] = b1[w] - mean * a;
        }
    }
    __syncthreads();
    const int r = tid;
    const float w0 = Wih1[r * 3], w1 = Wih1[r * 3 + 1], w2 = Wih1[r * 3 + 2];
    const float bias = bih1[r] + bhh1[r];
    float* pre = g_pre + bx * (SEQ * G4);
    for (int s = 0; s < SEQ; s++) {
        int n = s & 127, t = s >> 7;
        const float* xp = x + (n * 48 + bx * 16 + t) * 3;
        float a = a1[t], bb = bb1[t];
        float x0 = fmaf(xp[0], a, bb);
        float x1 = fmaf(xp[1], a, bb);
        float x2 = fmaf(xp[2], a, bb);
        pre[s * G4 + r] = bias + w0 * x0 + w1 * x1 + w2 * x2;
    }
}

// cluster pair per branch; rank q owns k-half [64q,64q+64) with weights in regs
__global__ void __launch_bounds__(512, 1) __cluster_dims__(2, 1, 1)
k_scan2(const float* __restrict__ Whh,
        const float* __restrict__ h0s, const float* __restrict__ c0s,
        float* __restrict__ dout, int layer)
{
    const int tid = threadIdx.x;
    unsigned int q;
    asm("mov.u32 %0, %%cluster_ctarank;" : "=r"(q));
    const int b = blockIdx.x >> 1;

    __shared__ __align__(16) float sh_h[64];
    __shared__ float sh_mine[G4];
    __shared__ __align__(16) float sh_recv[2][G4];

    // peer addresses for the two recv buffers
    unsigned int l0, p0, p1;
    asm("{ .reg .u64 t; cvta.to.shared.u64 t, %1; cvt.u32.u64 %0, t; }"
        : "=r"(l0) : "l"(&sh_recv[0][0]));
    asm("mapa.shared::cluster.u32 %0, %1, %2;" : "=r"(p0) : "r"(l0), "r"(q ^ 1u));
    asm("mapa.shared::cluster.u32 %0, %1, %2;" : "=r"(p1) : "r"(l0 + (unsigned int)(G4 * 4)), "r"(q ^ 1u));

    // 64 weights per thread, packed as 32 f32x2
    unsigned long long w[32];
    {
        const ulonglong2* wp = (const ulonglong2*)(Whh + tid * 128 + q * 64);
        #pragma unroll
        for (int j = 0; j < 16; j++) { ulonglong2 t = wp[j]; w[2 * j] = t.x; w[2 * j + 1] = t.y; }
    }

    float c = 0.f;
    if (tid < 64) {
        sh_h[tid] = h0s[(2 * b + layer) * H + 64 * q + tid];
        c         = c0s[(2 * b + layer) * H + 64 * q + tid];
    }
    const float* __restrict__ pre = g_pre + b * (SEQ * G4);
    float* __restrict__ ob = layer ? (dout + b * (SEQ * H)) : (g_ys1 + b * (SEQ * H));

    asm volatile("barrier.cluster.arrive.aligned;" ::: "memory");
    asm volatile("barrier.cluster.wait.aligned;" ::: "memory");

    float pcur = (q == 0) ? pre[tid] : 0.f;

    for (int s = 0; s < SEQ; s++) {
        float pnext = 0.f;
        if (q == 0 && s + 1 < SEQ) pnext = pre[(s + 1) * G4 + tid];

        unsigned long long a0 = 0ull, a1 = 0ull;
        const ulonglong2* hp = (const ulonglong2*)sh_h;
        #pragma unroll
        for (int j = 0; j < 16; j++) {
            ulonglong2 h2 = hp[j];
            asm("fma.rn.f32x2 %0, %1, %2, %0;" : "+l"(a0) : "l"(w[2 * j]),     "l"(h2.x));
            asm("fma.rn.f32x2 %0, %1, %2, %0;" : "+l"(a1) : "l"(w[2 * j + 1]), "l"(h2.y));
        }
        float s00 = __uint_as_float((unsigned)a0);
        float s01 = __uint_as_float((unsigned)(a0 >> 32));
        float s10 = __uint_as_float((unsigned)a1);
        float s11 = __uint_as_float((unsigned)(a1 >> 32));
        float acc = pcur + ((s00 + s01) + (s10 + s11));

        sh_mine[tid] = acc;
        unsigned int paddr = ((s & 1) ? p1 : p0) + (unsigned int)tid * 4u;
        asm volatile("st.shared::cluster.f32 [%0], %1;" :: "r"(paddr), "f"(acc) : "memory");

        asm volatile("barrier.cluster.arrive.aligned;" ::: "memory");
        asm volatile("barrier.cluster.wait.aligned;" ::: "memory");

        if (tid < 64) {
            const float* rv = sh_recv[s & 1];
            int u = q * 64 + tid;
            float gi = sh_mine[u]       + rv[u];
            float gf = sh_mine[128 + u] + rv[128 + u];
            float gg = sh_mine[256 + u] + rv[256 + u];
            float go = sh_mine[384 + u] + rv[384 + u];
            float ig = sigm(gi), fg = sigm(gf), og = sigm(go);
            float gv = tanhf(gg);
            c = fg * c + ig * gv;
            float h = og * tanhf(c);
            sh_h[tid] = h;
            ob[s * H + u] = h;
        }
        __syncthreads();
        pcur = pnext;
    }
}

__global__ void __launch_bounds__(512) k_bn2(
    const float* __restrict__ g2, const float* __restrict__ b2)
{
    const int b = blockIdx.x, w = threadIdx.x >> 5, lane = threadIdx.x & 31;
    const float* ys = g_ys1 + b * (SEQ * H);
    for (int ch = w; ch < H; ch += 16) {
        float s = 0.f, sq = 0.f;
        for (int m = lane; m < 2048; m += 32) {
            int a = m >> 7, l = m & 127;
            float v = ys[(a * 128 + ch) * H + l];
            s += v; sq += v * v;
        }
        #pragma unroll
        for (int o = 16; o; o >>= 1) {
            s  += __shfl_xor_sync(0xffffffffu, s, o);
            sq += __shfl_xor_sync(0xffffffffu, sq, o);
        }
        if (lane == 0) {
            float mean = s * (1.0f / 2048.0f);
            float var  = sq * (1.0f / 2048.0f) - mean * mean;
            float a2 = g2[ch] * rsqrtf(var + 1e-5f);
            g_a2[b * H + ch]  = a2;
            g_bb2[b * H + ch] = b2[ch] - mean * a2;
        }
    }
}

__global__ void __launch_bounds__(512) k_pre2(
    const float* __restrict__ bih2, const float* __restrict__ bhh2)
{
    const int b = blockIdx.x >> 6, grp = blockIdx.x & 63, s0 = grp * 32;
    const int tid = threadIdx.x, r = tid;
    __shared__ float sh_x[32][128];
    const float* ys = g_ys1 + b * (SEQ * H);
    for (int i = tid; i < 32 * 128; i += 512) {
        int row = i >> 7, k = i & 127;
        int s2 = s0 + row;
        int ch = s2 >> 4;
        int s1 = ((s2 & 15) << 7) + ch;
        sh_x[row][k] = fmaf(g_a2[b * H + ch], ys[s1 * H + k], g_bb2[b * H + ch]);
    }
    __syncthreads();
    float acc[32];
    #pragma unroll
    for (int i = 0; i < 32; i++) acc[i] = 0.f;
    for (int k = 0; k < 128; k++) {
        float w = g_WT2[k * G4 + r];
        #pragma unroll
        for (int i = 0; i < 32; i++) acc[i] = fmaf(w, sh_x[i][k], acc[i]);
    }
    float bias = bih2[r] + bhh2[r];
    float* pre = g_pre + b * (SEQ * G4);
    #pragma unroll
    for (int i = 0; i < 32; i++) pre[(s0 + i) * G4 + r] = acc[i] + bias;
}

extern "C" void kernel_launch(void* const* d_in, const int* in_sizes, int n_in,
                              void* d_out, int out_size)
{
    const float* x    = (const float*)d_in[0];
    const float* g1   = (const float*)d_in[1];
    const float* b1   = (const float*)d_in[2];
    const float* Wih1 = (const float*)d_in[3];
    const float* Whh1 = (const float*)d_in[4];
    const float* bih1 = (const float*)d_in[5];
    const float* bhh1 = (const float*)d_in[6];
    const float* g2   = (const float*)d_in[7];
    const float* b2   = (const float*)d_in[8];
    const float* Wih2 = (const float*)d_in[9];
    const float* Whh2 = (const float*)d_in[10];
    const float* bih2 = (const float*)d_in[11];
    const float* bhh2 = (const float*)d_in[12];
    const float* h0s  = (const float*)d_in[13];
    const float* c0s  = (const float*)d_in[14];
    float* out = (float*)d_out;

    k_prep<<<4, 512>>>(x, g1, b1, Wih1, bih1, bhh1, Wih2);
    k_scan2<<<NB * 2, 512>>>(Whh1, h0s, c0s, out, 0);
    k_bn2<<<NB, 512>>>(g2, b2);
    k_pre2<<<NB * 64, 512>>>(bih2, bhh2);
    k_scan2<<<NB * 2, 512>>>(Whh2, h0s, c0s, out, 1);
}

// round 5
// speedup vs baseline: 2.5007x; 1.1003x over previous
#include <cuda_runtime.h>
#include <cstdint>

#define H 128
#define NB 3
#define SEQ 2048
#define G4 512

__device__ float g_pre[NB * SEQ * G4];
__device__ float g_ys1[NB * SEQ * H];
__device__ float g_WT2[128 * G4];
__device__ float g_a2[NB * H];
__device__ float g_bb2[NB * H];

__device__ __forceinline__ float sigm(float x) {
    return __fdividef(1.0f, 1.0f + __expf(-x));
}
__device__ __forceinline__ float tanh_fast(float x) {
    return 2.0f * __fdividef(1.0f, 1.0f + __expf(-2.0f * x)) - 1.0f;
}

// grid 4: 0..2 BN1+pre1 per branch; 3 pack Wih2^T
__global__ void __launch_bounds__(512) k_prep(
    const float* __restrict__ x,
    const float* __restrict__ g1, const float* __restrict__ b1,
    const float* __restrict__ Wih1,
    const float* __restrict__ bih1, const float* __restrict__ bhh1,
    const float* __restrict__ Wih2)
{
    const int bx = blockIdx.x, tid = threadIdx.x;
    if (bx == 3) {
        for (int i = tid; i < 128 * G4; i += 512) {
            int k = i >> 9, r = i & 511;
            g_WT2[i] = Wih2[r * 128 + k];
        }
        return;
    }
    __shared__ float a1[16], bb1[16];
    const int w = tid >> 5, lane = tid & 31;
    {
        float s = 0.f, sq = 0.f;
        for (int m = lane; m < 384; m += 32) {
            int n = m / 3, d = m - 3 * n;
            float v = x[(n * 48 + bx * 16 + w) * 3 + d];
            s += v; sq += v * v;
        }
        #pragma unroll
        for (int o = 16; o; o >>= 1) {
            s  += __shfl_xor_sync(0xffffffffu, s, o);
            sq += __shfl_xor_sync(0xffffffffu, sq, o);
        }
        if (lane == 0) {
            float mean = s * (1.0f / 384.0f);
            float var  = sq * (1.0f / 384.0f) - mean * mean;
            float a = g1[w] * rsqrtf(var + 1e-5f);
            a1[w] = a; bb1[w] = b1[w] - mean * a;
        }
    }
    __syncthreads();
    const int r = tid;
    const float w0 = Wih1[r * 3], w1 = Wih1[r * 3 + 1], w2 = Wih1[r * 3 + 2];
    const float bias = bih1[r] + bhh1[r];
    float* pre = g_pre + bx * (SEQ * G4);
    #pragma unroll 4
    for (int s = 0; s < SEQ; s++) {
        int n = s & 127, t = s >> 7;
        const float* xp = x + (n * 48 + bx * 16 + t) * 3;
        float a = a1[t], bb = bb1[t];
        float x0 = fmaf(xp[0], a, bb);
        float x1 = fmaf(xp[1], a, bb);
        float x2 = fmaf(xp[2], a, bb);
        pre[s * G4 + r] = bias + w0 * x0 + w1 * x1 + w2 * x2;
    }
}

// cluster pair per branch; rank q owns k-half [64q,64q+64) with weights in regs.
// sync via double-buffered DSMEM partial push + mbarrier (16 per-warp arrives).
__global__ void __launch_bounds__(512, 1) __cluster_dims__(2, 1, 1)
k_scan2(const float* __restrict__ Whh,
        const float* __restrict__ h0s, const float* __restrict__ c0s,
        float* __restrict__ dout, int layer)
{
    const int tid = threadIdx.x;
    const int lane = tid & 31;
    unsigned int q;
    asm("mov.u32 %0, %%cluster_ctarank;" : "=r"(q));
    const int b = blockIdx.x >> 1;

    __shared__ __align__(16) float sh_h[64];
    __shared__ float sh_mine[G4];
    __shared__ __align__(16) float sh_recv[2][G4];
    __shared__ __align__(8) unsigned long long mbar[2];

    if (tid == 0) {
        unsigned int m0;
        asm("{ .reg .u64 t; cvta.to.shared.u64 t, %1; cvt.u32.u64 %0, t; }"
            : "=r"(m0) : "l"(&mbar[0]));
        asm volatile("mbarrier.init.shared.b64 [%0], %1;" :: "r"(m0), "r"(16u) : "memory");
        asm volatile("mbarrier.init.shared.b64 [%0], %1;" :: "r"(m0 + 8u), "r"(16u) : "memory");
    }

    // local/peer addresses
    unsigned int mb_l, mb_r, rv_l, rv_r;
    asm("{ .reg .u64 t; cvta.to.shared.u64 t, %1; cvt.u32.u64 %0, t; }"
        : "=r"(mb_l) : "l"(&mbar[0]));
    asm("{ .reg .u64 t; cvta.to.shared.u64 t, %1; cvt.u32.u64 %0, t; }"
        : "=r"(rv_l) : "l"(&sh_recv[0][0]));
    asm("mapa.shared::cluster.u32 %0, %1, %2;" : "=r"(mb_r) : "r"(mb_l), "r"(q ^ 1u));
    asm("mapa.shared::cluster.u32 %0, %1, %2;" : "=r"(rv_r) : "r"(rv_l), "r"(q ^ 1u));

    // 64 weights per thread, packed as 32 f32x2
    unsigned long long w[32];
    {
        const ulonglong2* wp = (const ulonglong2*)(Whh + tid * 128 + q * 64);
        #pragma unroll
        for (int j = 0; j < 16; j++) { ulonglong2 t = wp[j]; w[2 * j] = t.x; w[2 * j + 1] = t.y; }
    }

    float c = 0.f;
    if (tid < 64) {
        sh_h[tid] = h0s[(2 * b + layer) * H + 64 * q + tid];
        c         = c0s[(2 * b + layer) * H + 64 * q + tid];
    }
    const float* __restrict__ pre = g_pre + b * (SEQ * G4);
    float* __restrict__ ob = layer ? (dout + b * (SEQ * H)) : (g_ys1 + b * (SEQ * H));

    // cluster-wide: peer mbarrier init + sh_h visible before first use
    asm volatile("barrier.cluster.arrive.aligned;" ::: "memory");
    asm volatile("barrier.cluster.wait.aligned;" ::: "memory");

    float pcur = (q == 0) ? pre[tid] : 0.f;

    for (int s = 0; s < SEQ; s++) {
        float pnext = 0.f;
        if (q == 0 && s + 1 < SEQ) pnext = pre[(s + 1) * G4 + tid];

        unsigned long long a0 = 0ull, a1 = 0ull;
        const ulonglong2* hp = (const ulonglong2*)sh_h;
        #pragma unroll
        for (int j = 0; j < 16; j++) {
            ulonglong2 h2 = hp[j];
            asm("fma.rn.f32x2 %0, %1, %2, %0;" : "+l"(a0) : "l"(w[2 * j]),     "l"(h2.x));
            asm("fma.rn.f32x2 %0, %1, %2, %0;" : "+l"(a1) : "l"(w[2 * j + 1]), "l"(h2.y));
        }
        float s00 = __uint_as_float((unsigned)a0);
        float s01 = __uint_as_float((unsigned)(a0 >> 32));
        float s10 = __uint_as_float((unsigned)a1);
        float s11 = __uint_as_float((unsigned)(a1 >> 32));
        float acc = pcur + ((s00 + s01) + (s10 + s11));

        const int buf = s & 1;
        const unsigned int parity = (unsigned)((s >> 1) & 1);

        sh_mine[tid] = acc;
        asm volatile("st.shared::cluster.f32 [%0], %1;"
                     :: "r"(rv_r + (unsigned)buf * (G4 * 4u) + (unsigned)tid * 4u), "f"(acc)
                     : "memory");
        __syncwarp();
        if (lane == 0) {
            asm volatile("mbarrier.arrive.release.cluster.shared::cluster.b64 _, [%0];"
                         :: "r"(mb_r + (unsigned)buf * 8u) : "memory");
        }

        // wait for peer's 16 warp-arrives on our local mbar[buf]
        {
            unsigned int mba = mb_l + (unsigned)buf * 8u;
            unsigned int done = 0;
            while (!done) {
                asm volatile(
                    "{\n\t.reg .pred p;\n\t"
                    "mbarrier.try_wait.parity.acquire.cluster.shared::cta.b64 p, [%1], %2, 0x989680;\n\t"
                    "selp.b32 %0, 1, 0, p;\n\t}"
                    : "=r"(done) : "r"(mba), "r"(parity) : "memory");
            }
        }

        if (tid < 64) {
            const float* rv = sh_recv[buf];
            int u = q * 64 + tid;
            float gi = sh_mine[u]       + rv[u];
            float gf = sh_mine[128 + u] + rv[128 + u];
            float gg = sh_mine[256 + u] + rv[256 + u];
            float go = sh_mine[384 + u] + rv[384 + u];
            float ig = sigm(gi), fg = sigm(gf), og = sigm(go);
            float gv = tanh_fast(gg);
            c = fg * c + ig * gv;
            float h = og * tanh_fast(c);
            sh_h[tid] = h;
            ob[s * H + u] = h;
        }
        __syncthreads();
        pcur = pnext;
    }
}

__global__ void __launch_bounds__(512) k_bn2(
    const float* __restrict__ g2, const float* __restrict__ b2)
{
    const int b = blockIdx.x, w = threadIdx.x >> 5, lane = threadIdx.x & 31;
    const float* ys = g_ys1 + b * (SEQ * H);
    for (int ch = w; ch < H; ch += 16) {
        float s = 0.f, sq = 0.f;
        for (int m = lane; m < 2048; m += 32) {
            int a = m >> 7, l = m & 127;
            float v = ys[(a * 128 + ch) * H + l];
            s += v; sq += v * v;
        }
        #pragma unroll
        for (int o = 16; o; o >>= 1) {
            s  += __shfl_xor_sync(0xffffffffu, s, o);
            sq += __shfl_xor_sync(0xffffffffu, sq, o);
        }
        if (lane == 0) {
            float mean = s * (1.0f / 2048.0f);
            float var  = sq * (1.0f / 2048.0f) - mean * mean;
            float a2 = g2[ch] * rsqrtf(var + 1e-5f);
            g_a2[b * H + ch]  = a2;
            g_bb2[b * H + ch] = b2[ch] - mean * a2;
        }
    }
}

__global__ void __launch_bounds__(512) k_pre2(
    const float* __restrict__ bih2, const float* __restrict__ bhh2)
{
    const int b = blockIdx.x >> 6, grp = blockIdx.x & 63, s0 = grp * 32;
    const int tid = threadIdx.x, r = tid;
    __shared__ float sh_x[32][128];
    const float* ys = g_ys1 + b * (SEQ * H);
    for (int i = tid; i < 32 * 128; i += 512) {
        int row = i >> 7, k = i & 127;
        int s2 = s0 + row;
        int ch = s2 >> 4;
        int s1 = ((s2 & 15) << 7) + ch;
        sh_x[row][k] = fmaf(g_a2[b * H + ch], ys[s1 * H + k], g_bb2[b * H + ch]);
    }
    __syncthreads();
    float acc[32];
    #pragma unroll
    for (int i = 0; i < 32; i++) acc[i] = 0.f;
    for (int k = 0; k < 128; k++) {
        float w = g_WT2[k * G4 + r];
        #pragma unroll
        for (int i = 0; i < 32; i++) acc[i] = fmaf(w, sh_x[i][k], acc[i]);
    }
    float bias = bih2[r] + bhh2[r];
    float* pre = g_pre + b * (SEQ * G4);
    #pragma unroll
    for (int i = 0; i < 32; i++) pre[(s0 + i) * G4 + r] = acc[i] + bias;
}

extern "C" void kernel_launch(void* const* d_in, const int* in_sizes, int n_in,
                              void* d_out, int out_size)
{
    const float* x    = (const float*)d_in[0];
    const float* g1   = (const float*)d_in[1];
    const float* b1   = (const float*)d_in[2];
    const float* Wih1 = (const float*)d_in[3];
    const float* Whh1 = (const float*)d_in[4];
    const float* bih1 = (const float*)d_in[5];
    const float* bhh1 = (const float*)d_in[6];
    const float* g2   = (const float*)d_in[7];
    const float* b2   = (const float*)d_in[8];
    const float* Wih2 = (const float*)d_in[9];
    const float* Whh2 = (const float*)d_in[10];
    const float* bih2 = (const float*)d_in[11];
    const float* bhh2 = (const float*)d_in[12];
    const float* h0s  = (const float*)d_in[13];
    const float* c0s  = (const float*)d_in[14];
    float* out = (float*)d_out;

    k_prep<<<4, 512>>>(x, g1, b1, Wih1, bih1, bhh1, Wih2);
    k_scan2<<<NB * 2, 512>>>(Whh1, h0s, c0s, out, 0);
    k_bn2<<<NB, 512>>>(g2, b2);
    k_pre2<<<NB * 64, 512>>>(bih2, bhh2);
    k_scan2<<<NB * 2, 512>>>(Whh2, h0s, c0s, out, 1);
}